// round 17
// baseline (speedup 1.0000x reference)
#include <cuda_runtime.h>

// FocalTreeMinLoss on GB300 (sm_103a).
// Tree: leaf l -> parent2 = 41 + l%9, grandparent = 50 + l%3.
//
// Identity: per-element focal-BCE term is
//   t=0: g(x),  t=1: g(-x),  g(y) = softplus(y)*sigmoid(y)^2
// With c = y*log2e, v = 2^c, d = 1+v:  g = ln2 * log2(d) * (v/d)^2
//
// Base-plus-correction: all 53 classes as t=0 with x = pred (leaf) /
// m2 (2nd-level max incl self) / m1 (top max); then fix the 3 path classes.
//
// cp.async SMEM staging ring (zero register cost for pipeline depth).
// THIS ROUND: 4 px/thread with cp.async.cg 16B — per-pixel load machinery
// halves and the fill path bypasses L1. Ring depth 12 (48 KB/CTA, 3 CTA/SM).

#define BATCH 4
#define STAGES 12
#define FIXSCALE 16777216.0  // 2^24
#define LOG2E 1.4426950408889634f
#define LN2   0.6931471805599453f

typedef unsigned long long u64;

#define ONE2   0x3F8000003F800000ULL
#define TWO2   0x4000000040000000ULL
#define LOG2E2 0x3FB8AA3B3FB8AA3BULL

__device__ unsigned long long g_acc;     // zero-init; reset by last block
__device__ unsigned int       g_ticket;  // zero-init; reset by last block

// ---- channel consumption order: groups k=0..8 = {k,k+9,...,41+k}, then 50..52
__host__ __device__ constexpr int seq_chan(int p) {
    if (p >= 50) return p;
    const int g  = (p < 30) ? (p / 6) : (5 + (p - 30) / 5);
    const int j  = (p < 30) ? (p % 6) : ((p - 30) % 5);
    const int nl = (g < 5) ? 5 : 4;
    return (j < nl) ? (g + 9 * j) : (41 + g);
}
__host__ __device__ constexpr int pos0(int k) {
    return (k < 5) ? 6 * k : 30 + 5 * (k - 5);
}

__device__ __forceinline__ void cp_async16(unsigned saddr, const void* gaddr) {
    asm volatile("cp.async.cg.shared.global [%0], [%1], 16;"
                 :: "r"(saddr), "l"(gaddr) : "memory");
}
#define CP_COMMIT()  asm volatile("cp.async.commit_group;"  ::: "memory")
#define CP_WAIT()    asm volatile("cp.async.wait_group 11;" ::: "memory")

__device__ __forceinline__ void lds4(unsigned addr, float& a, float& b,
                                     float& c, float& d) {
    asm volatile("ld.shared.v4.f32 {%0, %1, %2, %3}, [%4];"
                 : "=f"(a), "=f"(b), "=f"(c), "=f"(d) : "r"(addr));
}

__device__ __forceinline__ float ex2f(float x) {
    float v; asm("ex2.approx.ftz.f32 %0, %1;" : "=f"(v) : "f"(x)); return v;
}
__device__ __forceinline__ float lg2f(float x) {
    float v; asm("lg2.approx.ftz.f32 %0, %1;" : "=f"(v) : "f"(x)); return v;
}
__device__ __forceinline__ u64 pk2(float a, float b) {
    u64 r; asm("mov.b64 %0, {%1, %2};" : "=l"(r) : "f"(a), "f"(b)); return r;
}
__device__ __forceinline__ void upk2(u64 v, float& a, float& b) {
    asm("mov.b64 {%0, %1}, %2;" : "=f"(a), "=f"(b) : "l"(v));
}
__device__ __forceinline__ u64 addx2(u64 a, u64 b) {
    u64 r; asm("add.rn.f32x2 %0, %1, %2;" : "=l"(r) : "l"(a), "l"(b)); return r;
}
__device__ __forceinline__ u64 mulx2(u64 a, u64 b) {
    u64 r; asm("mul.rn.f32x2 %0, %1, %2;" : "=l"(r) : "l"(a), "l"(b)); return r;
}
__device__ __forceinline__ u64 fmax2p(u64 a, u64 b, u64 c) {
    u64 r; asm("fma.rn.f32x2 %0, %1, %2, %3;" : "=l"(r) : "l"(a), "l"(b), "l"(c));
    return r;
}

// accp += log2(1+e^x)*sigmoid(x)^2 for both lanes; inputs c = x*log2e
__device__ __forceinline__ void g2acc2(float c0, float c1, u64& accp) {
    float v0 = ex2f(c0), v1 = ex2f(c1);            // 2x MUFU.EX2
    u64 vp = pk2(v0, v1);
    u64 dp = addx2(vp, ONE2);                      // d = 1+v (packed)
    float d0, d1; upk2(dp, d0, d1);
    float L0 = lg2f(d0), L1 = lg2f(d1);            // 2x MUFU.LG2
    // negated rcp seed; iteration keeps q negated: q <- q*fma(d,q,2)
    int q0 = (int)0xFEF311C3 - __float_as_int(d0);
    int q1 = (int)0xFEF311C3 - __float_as_int(d1);
    u64 qp = pk2(__int_as_float(q0), __int_as_float(q1));
    qp = mulx2(qp, fmax2p(dp, qp, TWO2));          // Newton 1
    qp = mulx2(qp, fmax2p(dp, qp, TWO2));          // Newton 2 (~1e-6)
    u64 sp = mulx2(vp, qp);                        // = -sigmoid (packed)
    u64 Ls = mulx2(pk2(L0, L1), sp);               // = -L*s
    accp = fmax2p(Ls, sp, accp);                   // += L*s^2 (sign cancels)
}

__global__ void __launch_bounds__(256, 3) focal_main(
    const float* __restrict__ cls, const int* __restrict__ label,
    int HW, float* __restrict__ out, int nblocks, double scale)
{
    __shared__ float4 ring[STAGES][256];           // 48 KB staging ring

    int tid = threadIdx.x;
    int p4  = blockIdx.x * blockDim.x + tid;       // float4 index in batch
    int b   = blockIdx.y;
    int n4  = HW >> 2;
    float sum = 0.f;

    if (p4 < n4) {
        const float4* base4 = reinterpret_cast<const float4*>(
            cls + (size_t)b * 53 * HW) + p4;
        const float* bs = cls + (size_t)b * 53 * HW + (size_t)p4 * 4;

        unsigned sbase = (unsigned)__cvta_generic_to_shared(&ring[0][0])
                       + (unsigned)tid * 16u;

        // labels + per-pixel vlab gathers (issued early, consumed last)
        int4 lb = __ldg(reinterpret_cast<const int4*>(label + (size_t)b * HW) + p4);
        int labs[4] = {lb.x, lb.y, lb.z, lb.w};
        int i9[4], i3[4];
        float vlab[4];
#pragma unroll
        for (int px = 0; px < 4; px++) {
            i9[px] = labs[px] % 9; i3[px] = labs[px] % 3;
            vlab[px] = __ldg(bs + px + (size_t)labs[px] * HW) * LOG2E;
        }

        // prologue: stage channels at positions 0..STAGES-1
#pragma unroll
        for (int p = 0; p < STAGES; p++) {
            cp_async16(sbase + (unsigned)(p * 4096),
                       base4 + (size_t)seq_chan(p) * n4);
            CP_COMMIT();
        }

        u64 accP0 = 0ull, accP1 = 0ull, accN0 = 0ull, accN1 = 0ull;
        float m1p[3][4];
#pragma unroll
        for (int j = 0; j < 3; j++)
#pragma unroll
            for (int px = 0; px < 4; px++) m1p[j][px] = -3.4e38f;
        float m2s[4] = {0.f, 0.f, 0.f, 0.f};
        float vpb[4] = {0.f, 0.f, 0.f, 0.f};
        float tv[3][4];

        // ---- group-ordered consumption ----
#pragma unroll
        for (int k = 0; k < 9; k++) {
            const int nl = (k < 5) ? 5 : 4;
            float gm[4] = {-3.4e38f, -3.4e38f, -3.4e38f, -3.4e38f};
            float x2[4] = {0.f, 0.f, 0.f, 0.f};
#pragma unroll
            for (int j = 0; j <= nl; j++) {
                const int pos = pos0(k) + j;
                CP_WAIT();                         // completed >= pos+1
                float a0, b0, c0, d0;
                lds4(sbase + (unsigned)((pos % STAGES) * 4096), a0, b0, c0, d0);
                // prefetch pos+STAGES (empty commit in tail keeps invariant)
                if (pos + STAGES < 53)
                    cp_async16(sbase + (unsigned)((pos % STAGES) * 4096),
                               base4 + (size_t)seq_chan(pos + STAGES) * n4);
                CP_COMMIT();

                u64 x01 = mulx2(pk2(a0, b0), LOG2E2);
                u64 x23 = mulx2(pk2(c0, d0), LOG2E2);
                float xa, xb, xc, xd;
                upk2(x01, xa, xb); upk2(x23, xc, xd);
                if (j < nl) {
                    g2acc2(xa, xb, accP0);
                    g2acc2(xc, xd, accP1);
                    gm[0] = fmaxf(gm[0], xa); gm[1] = fmaxf(gm[1], xb);
                    gm[2] = fmaxf(gm[2], xc); gm[3] = fmaxf(gm[3], xd);
                } else { x2[0] = xa; x2[1] = xb; x2[2] = xc; x2[3] = xd; }
            }
            float m2k[4];
#pragma unroll
            for (int px = 0; px < 4; px++) {
                m2k[px] = fmaxf(gm[px], x2[px]);
                m1p[k % 3][px] = fmaxf(m1p[k % 3][px], m2k[px]);
                bool sel = (i9[px] == k);
                m2s[px] = sel ? m2k[px] : m2s[px];
                vpb[px] = sel ? x2[px]  : vpb[px];
            }
            g2acc2(m2k[0], m2k[1], accP0);         // base term, class 41+k
            g2acc2(m2k[2], m2k[3], accP1);
        }

        // ---- top channels (positions 50..52) ----
#pragma unroll
        for (int j = 0; j < 3; j++) {
            const int pos = 50 + j;
            CP_WAIT();
            float a0, b0, c0, d0;
            lds4(sbase + (unsigned)((pos % STAGES) * 4096), a0, b0, c0, d0);
            CP_COMMIT();                           // empty: keep invariant
            tv[j][0] = a0 * LOG2E; tv[j][1] = b0 * LOG2E;
            tv[j][2] = c0 * LOG2E; tv[j][3] = d0 * LOG2E;
        }
        float m1[3][4];
#pragma unroll
        for (int j = 0; j < 3; j++)
#pragma unroll
            for (int px = 0; px < 4; px++)
                m1[j][px] = fmaxf(tv[j][px], m1p[j][px]);
#pragma unroll
        for (int j = 0; j < 3; j++) {
            g2acc2(m1[j][0], m1[j][1], accP0);
            g2acc2(m1[j][2], m1[j][3], accP1);
        }

        // ---- corrections for the 3 path classes per pixel ----
        float mnL[4], mnS[4], vpc[4], m1s[4];
#pragma unroll
        for (int px = 0; px < 4; px++) {
            float vc = (i3[px] == 1) ? tv[1][px] : tv[0][px];
            vc       = (i3[px] == 2) ? tv[2][px] : vc;
            float ms = (i3[px] == 1) ? m1[1][px] : m1[0][px];
            ms       = (i3[px] == 2) ? m1[2][px] : ms;
            vpc[px] = vc; m1s[px] = ms;
            mnS[px] = fminf(vpb[px], vc);
            mnL[px] = fminf(vlab[px], mnS[px]);
        }
        g2acc2(-mnL[0], -mnL[1], accP0);  g2acc2(-mnL[2], -mnL[3], accP1);
        g2acc2(-mnS[0], -mnS[1], accP0);  g2acc2(-mnS[2], -mnS[3], accP1);
        g2acc2(-vpc[0], -vpc[1], accP0);  g2acc2(-vpc[2], -vpc[3], accP1);
        g2acc2(vlab[0], vlab[1], accN0);  g2acc2(vlab[2], vlab[3], accN1);
        g2acc2(m2s[0],  m2s[1],  accN0);  g2acc2(m2s[2],  m2s[3],  accN1);
        g2acc2(m1s[0],  m1s[1],  accN0);  g2acc2(m1s[2],  m1s[3],  accN1);

        float p0, p1, p2v, p3, n0, n1, n2v, n3;
        upk2(accP0, p0, p1); upk2(accP1, p2v, p3);
        upk2(accN0, n0, n1); upk2(accN1, n2v, n3);
        sum = (((p0 + p1) + (p2v + p3)) - ((n0 + n1) + (n2v + n3))) * LN2;
    }

    // ---- block reduction (256 threads = 8 warps) ----
#pragma unroll
    for (int o = 16; o > 0; o >>= 1)
        sum += __shfl_down_sync(0xffffffffu, sum, o);
    __shared__ float ws[8];
    int lane = threadIdx.x & 31, wid = threadIdx.x >> 5;
    if (lane == 0) ws[wid] = sum;
    __syncthreads();
    if (wid == 0) {
        float s = (lane < 8) ? ws[lane] : 0.f;
#pragma unroll
        for (int o = 4; o > 0; o >>= 1)
            s += __shfl_down_sync(0xffffffffu, s, o);
        if (lane == 0) {
            unsigned long long v =
                (unsigned long long)__float2ll_rn(s * (float)FIXSCALE);
            atomicAdd(&g_acc, v);
            __threadfence();
            unsigned int t = atomicInc(&g_ticket, 0xffffffffu);
            if (t == (unsigned int)(nblocks - 1)) {
                unsigned long long a = atomicExch(&g_acc, 0ull);
                g_ticket = 0u;
                out[0] = (float)((double)a * scale);
            }
        }
    }
}

extern "C" void kernel_launch(void* const* d_in, const int* in_sizes, int n_in,
                              void* d_out, int out_size)
{
    const float* cls   = (const float*)d_in[0];
    const int*   label = (const int*)d_in[1];
    int N  = in_sizes[1];        // B*H*W
    int HW = N / BATCH;          // H*W
    int n4 = HW >> 2;

    dim3 grid((n4 + 255) / 256, BATCH);
    int nblocks = grid.x * grid.y;
    double scale = 1.0 / ((double)in_sizes[0] * FIXSCALE);
    focal_main<<<grid, 256>>>(cls, label, HW, (float*)d_out, nblocks, scale);
}